// round 1
// baseline (speedup 1.0000x reference)
#include <cuda_runtime.h>
#include <math.h>

// Problem constants
#define NSEQ 32
#define NHEAD 32
#define NKV 8
#define HPG 4            // heads per kv head (GQA)
#define DH 128           // head size
#define BS 16            // tokens per block
#define MAXB 256         // max blocks per seq
#define CHUNK_BLOCKS 64  // blocks per KV chunk
#define CHUNK_TOK (CHUNK_BLOCKS * BS)  // 1024
#define NCHUNK 4
#define QK_SCALE 0.08838834764831845f

// Split-KV partial scratch (allocation-free: __device__ globals)
__device__ float  g_pacc[NSEQ * NKV * NCHUNK * HPG * DH];   // 2 MB
__device__ float2 g_pml [NSEQ * NKV * NCHUNK * HPG];

__global__ __launch_bounds__(256) void pa_chunk_kernel(
    const float* __restrict__ q,    // [S, 32, 128]
    const float* __restrict__ kc,   // [NB, 8, 16, 16, 8]  (per (b,g): 2048 contiguous floats)
    const float* __restrict__ vc,   // [NB, 8, 128, 16]    (per (b,g): 2048 contiguous floats)
    const int*   __restrict__ bt,   // [S, 256]
    const int*   __restrict__ cl)   // [S]
{
    const int c = blockIdx.x, g = blockIdx.y, s = blockIdx.z;
    const int len = cl[s];
    const int chunk_start = c * CHUNK_TOK;
    if (chunk_start >= len) return;
    const int n_tok = min(len - chunk_start, CHUNK_TOK);
    const int n_blk = (n_tok + BS - 1) / BS;

    const int tid = threadIdx.x;
    // QK role: token qt (0..15), dim-part dpart (0..15, 8 dims each)
    const int qt = tid >> 4;
    const int dpart = tid & 15;
    // PV role: output dim pd (0..127), token-half (0..1, 8 tokens each)
    const int half = tid & 1;
    const int pd = tid >> 1;

    __shared__ float logit_s[HPG * BS];
    __shared__ float p_s[HPG * BS];
    __shared__ float cf_s[HPG];
    __shared__ float m_s[HPG], l_s[HPG];
    if (tid < HPG) { m_s[tid] = -1e30f; l_s[tid] = 0.f; }

    // Q in registers (loop invariant): qreg[h][j] = q[s][g*4+h][dpart*8+j]
    float qreg[HPG][8];
    {
        const float* qb = q + ((size_t)s * NHEAD + g * HPG) * DH + dpart * 8;
#pragma unroll
        for (int h = 0; h < HPG; h++)
#pragma unroll
            for (int j = 0; j < 8; j++)
                qreg[h][j] = __ldg(qb + h * DH + j);
    }
    float acc[HPG] = {0.f, 0.f, 0.f, 0.f};

    const int* btrow = bt + s * MAXB + c * CHUNK_BLOCKS;
    // K offset within (block,g) slab: (d/8)*128 + t*8 + d%8 -> dpart*128 + qt*8
    const int koff = dpart * 128 + qt * 8;
    // V offset: d*16 + half*8 == tid*8
    const int voff = tid * 8;

    // Prologue: load block 0 into "current" registers
    float4 ka0, ka1, va0, va1;
    {
        const int phys = btrow[0];
        const float* kp = kc + ((size_t)phys * NKV + g) * 2048 + koff;
        ka0 = *(const float4*)(kp);
        ka1 = *(const float4*)(kp + 4);
        const float* vp = vc + ((size_t)phys * NKV + g) * 2048 + voff;
        va0 = *(const float4*)(vp);
        va1 = *(const float4*)(vp + 4);
    }
    __syncthreads();  // m_s/l_s init visible

    for (int i = 0; i < n_blk; i++) {
        // Prefetch next block (clamped: harmless duplicate read on last iter)
        const int physn = btrow[min(i + 1, n_blk - 1)];
        const float* kp = kc + ((size_t)physn * NKV + g) * 2048 + koff;
        const float4 kb0 = *(const float4*)(kp);
        const float4 kb1 = *(const float4*)(kp + 4);
        const float* vp = vc + ((size_t)physn * NKV + g) * 2048 + voff;
        const float4 vb0 = *(const float4*)(vp);
        const float4 vb1 = *(const float4*)(vp + 4);

        // ---- QK: 4 heads x 16 tokens, dot over 128 dims ----
        const float kk[8] = {ka0.x, ka0.y, ka0.z, ka0.w, ka1.x, ka1.y, ka1.z, ka1.w};
        float lg[HPG];
#pragma unroll
        for (int h = 0; h < HPG; h++) {
            float t = 0.f;
#pragma unroll
            for (int j = 0; j < 8; j++) t = fmaf(kk[j], qreg[h][j], t);
            // butterfly sum over the 16 lanes sharing this token
#pragma unroll
            for (int o = 1; o < 16; o <<= 1) t += __shfl_xor_sync(0xffffffffu, t, o);
            lg[h] = t;
        }
        if (dpart == 0) {
#pragma unroll
            for (int h = 0; h < HPG; h++) logit_s[h * BS + qt] = lg[h];
        }
        __syncthreads();

        // ---- Online softmax (warps 0-1: 4 heads x 16 tokens) ----
        if (tid < 64) {
            const int h = tid >> 4, t = tid & 15;
            const bool valid = (i * BS + t) < n_tok;
            const float lgv = valid ? logit_s[h * BS + t] * QK_SCALE : -1e30f;
            float mb = lgv;
#pragma unroll
            for (int o = 1; o < 16; o <<= 1) mb = fmaxf(mb, __shfl_xor_sync(0xffffffffu, mb, o));
            const float m_old = m_s[h];
            const float m_new = fmaxf(m_old, mb);
            const float p = valid ? __expf(lgv - m_new) : 0.f;
            float ps = p;
#pragma unroll
            for (int o = 1; o < 16; o <<= 1) ps += __shfl_xor_sync(0xffffffffu, ps, o);
            p_s[h * BS + t] = p;
            if (t == 0) {
                const float cf = __expf(m_old - m_new);
                cf_s[h] = cf;
                m_s[h] = m_new;
                l_s[h] = l_s[h] * cf + ps;
            }
        }
        __syncthreads();

        // ---- PV: acc[h][pd] = acc*cf + sum_t p[h][t] * v[pd][t] (my 8-token half) ----
        const float vv[8] = {va0.x, va0.y, va0.z, va0.w, va1.x, va1.y, va1.z, va1.w};
        const float* pr = p_s + half * 8;
#pragma unroll
        for (int h = 0; h < HPG; h++) {
            float a = acc[h] * cf_s[h];
#pragma unroll
            for (int j = 0; j < 8; j++) a = fmaf(pr[h * BS + j], vv[j], a);
            acc[h] = a;
        }
        __syncthreads();  // p_s/cf_s/m_s consumed before next iteration rewrites

        ka0 = kb0; ka1 = kb1; va0 = vb0; va1 = vb1;
    }

    // ---- Write partials ----
    const int base = ((s * NKV + g) * NCHUNK + c) * HPG;
#pragma unroll
    for (int h = 0; h < HPG; h++) {
        const float tot = acc[h] + __shfl_xor_sync(0xffffffffu, acc[h], 1);
        if (half == 0) g_pacc[(size_t)(base + h) * DH + pd] = tot;
    }
    if (tid < 64 && (tid & 15) == 0) {
        const int h = tid >> 4;
        g_pml[base + h] = make_float2(m_s[h], l_s[h]);
    }
}

__global__ __launch_bounds__(512) void pa_combine_kernel(
    const int* __restrict__ cl, float* __restrict__ out)
{
    const int g = blockIdx.x, s = blockIdx.y;
    const int tid = threadIdx.x;
    const int h = tid >> 7, d = tid & 127;
    const int len = cl[s];
    const int nc = min(NCHUNK, (len + CHUNK_TOK - 1) / CHUNK_TOK);
    const int base = (s * NKV + g) * NCHUNK;

    float2 ml[NCHUNK];
    float M = -1e30f;
    for (int c = 0; c < nc; c++) {
        ml[c] = g_pml[(base + c) * HPG + h];
        M = fmaxf(M, ml[c].x);
    }
    float L = 0.f, o = 0.f;
    for (int c = 0; c < nc; c++) {
        const float w = __expf(ml[c].x - M);
        L += ml[c].y * w;
        o += g_pacc[(size_t)((base + c) * HPG + h) * DH + d] * w;
    }
    out[((size_t)s * NHEAD + g * HPG + h) * DH + d] = o / L;
}

extern "C" void kernel_launch(void* const* d_in, const int* in_sizes, int n_in,
                              void* d_out, int out_size)
{
    const float* q  = (const float*)d_in[0];
    const float* kc = (const float*)d_in[1];
    const float* vc = (const float*)d_in[2];
    const int*   bt = (const int*)d_in[3];
    const int*   cl = (const int*)d_in[4];
    float* out = (float*)d_out;

    dim3 grid1(NCHUNK, NKV, NSEQ);   // 4 x 8 x 32 = 1024 CTAs
    pa_chunk_kernel<<<grid1, 256>>>(q, kc, vc, bt, cl);
    dim3 grid2(NKV, NSEQ);           // 8 x 32 = 256 CTAs
    pa_combine_kernel<<<grid2, 512>>>(cl, out);
}

// round 2
// speedup vs baseline: 1.4375x; 1.4375x over previous
#include <cuda_runtime.h>
#include <math.h>

// Problem constants
#define NSEQ 32
#define NHEAD 32
#define NKV 8
#define HPG 4            // heads per kv head (GQA)
#define DH 128           // head size
#define BS 16            // tokens per block
#define MAXB 256         // max blocks per seq
#define CB 32            // blocks per chunk
#define CT (CB * BS)     // 512 tokens per chunk
#define NCHUNK 8
#define QK_SCALE 0.08838834764831845f

// Split-KV partial scratch (allocation-free: __device__ globals)
__device__ float  g_pacc[NSEQ * NKV * NCHUNK * HPG * DH];   // 4 MB
__device__ float2 g_pml [NSEQ * NKV * NCHUNK * HPG];

__global__ __launch_bounds__(256) void pa_chunk_kernel(
    const float* __restrict__ q,    // [S, 32, 128]
    const float* __restrict__ kc,   // [NB, 8, 16, 16, 8]  (per (b,g): 2048 contiguous floats)
    const float* __restrict__ vc,   // [NB, 8, 128, 16]    (per (b,g): 2048 contiguous floats)
    const int*   __restrict__ bt,   // [S, 256]
    const int*   __restrict__ cl)   // [S]
{
    const int c = blockIdx.x, g = blockIdx.y, s = blockIdx.z;
    const int len = cl[s];
    if (c * CT >= len) return;
    const int n_tok = min(len - c * CT, CT);
    const int n_blk = (n_tok + BS - 1) / BS;
    const int tid = threadIdx.x;

    __shared__ __align__(16) float ls[HPG * CT];  // logits, then probs (8 KB)
    __shared__ float red[8], red2[8];
    __shared__ int bt_s[CB];

    if (tid < CB) bt_s[tid] = bt[s * MAXB + c * CB + tid];

    // ================= Phase 1: K stream -> logits (barrier-free loop) ======
    const int qt = tid >> 4;      // token within block (0..15)
    const int dpart = tid & 15;   // 8-dim group (0..15)
    float qreg[HPG][8];
    {
        const float* qb = q + ((size_t)s * NHEAD + g * HPG) * DH + dpart * 8;
#pragma unroll
        for (int h = 0; h < HPG; h++)
#pragma unroll
            for (int j = 0; j < 8; j++)
                qreg[h][j] = __ldg(qb + h * DH + j);
    }
    __syncthreads();  // bt_s ready

    const int koff = dpart * 128 + qt * 8;  // (d/8)*128 + t*8 within (blk,g) slab
    float4 kb[4][2];
#pragma unroll
    for (int p = 0; p < 4; p++) {
        if (p < n_blk) {
            const float* kp = kc + ((size_t)bt_s[p] * NKV + g) * 2048 + koff;
            kb[p][0] = *(const float4*)kp;
            kb[p][1] = *(const float4*)(kp + 4);
        }
    }

    {
        int i = 0;
        for (; i + 4 <= n_blk; i += 4) {
#pragma unroll
            for (int u = 0; u < 4; u++) {
                const float4 a0 = kb[u][0], a1 = kb[u][1];
                if (i + u + 4 < n_blk) {
                    const float* kp = kc + ((size_t)bt_s[i + u + 4] * NKV + g) * 2048 + koff;
                    kb[u][0] = *(const float4*)kp;
                    kb[u][1] = *(const float4*)(kp + 4);
                }
                const float kk[8] = {a0.x, a0.y, a0.z, a0.w, a1.x, a1.y, a1.z, a1.w};
#pragma unroll
                for (int h = 0; h < HPG; h++) {
                    float t = 0.f;
#pragma unroll
                    for (int j = 0; j < 8; j++) t = fmaf(kk[j], qreg[h][j], t);
#pragma unroll
                    for (int o = 1; o < 16; o <<= 1)
                        t += __shfl_xor_sync(0xffffffffu, t, o);
                    if (dpart == 0) ls[h * CT + (i + u) * BS + qt] = t;
                }
            }
        }
        const int rem = n_blk - i;
#pragma unroll
        for (int u = 0; u < 3; u++) {
            if (u < rem) {
                const float4 a0 = kb[u][0], a1 = kb[u][1];
                const float kk[8] = {a0.x, a0.y, a0.z, a0.w, a1.x, a1.y, a1.z, a1.w};
#pragma unroll
                for (int h = 0; h < HPG; h++) {
                    float t = 0.f;
#pragma unroll
                    for (int j = 0; j < 8; j++) t = fmaf(kk[j], qreg[h][j], t);
#pragma unroll
                    for (int o = 1; o < 16; o <<= 1)
                        t += __shfl_xor_sync(0xffffffffu, t, o);
                    if (dpart == 0) ls[h * CT + (i + u) * BS + qt] = t;
                }
            }
        }
    }
    __syncthreads();

    // ================= Phase 2: one-shot softmax over the chunk =============
    const int h2 = tid >> 6;   // head (64 threads each)
    const int t2 = tid & 63;
    float vals[8];
    float lmax = -1e30f;
#pragma unroll
    for (int k = 0; k < 8; k++) {
        const int tok = t2 + 64 * k;
        vals[k] = (tok < n_tok) ? ls[h2 * CT + tok] * QK_SCALE : -1e30f;
        lmax = fmaxf(lmax, vals[k]);
    }
#pragma unroll
    for (int o = 1; o < 32; o <<= 1)
        lmax = fmaxf(lmax, __shfl_xor_sync(0xffffffffu, lmax, o));
    if ((tid & 31) == 0) red[tid >> 5] = lmax;
    __syncthreads();
    const float m = fmaxf(red[h2 * 2], red[h2 * 2 + 1]);
    float lsum = 0.f;
#pragma unroll
    for (int k = 0; k < 8; k++) {
        const int tok = t2 + 64 * k;
        const float p = (tok < n_tok) ? __expf(vals[k] - m) : 0.f;
        ls[h2 * CT + tok] = p;
        lsum += p;
    }
#pragma unroll
    for (int o = 1; o < 32; o <<= 1)
        lsum += __shfl_xor_sync(0xffffffffu, lsum, o);
    if ((tid & 31) == 0) red2[tid >> 5] = lsum;
    __syncthreads();  // probs + red2 visible
    if (t2 == 0) {
        const int base = ((s * NKV + g) * NCHUNK + c) * HPG;
        g_pml[base + h2] = make_float2(m, red2[h2 * 2] + red2[h2 * 2 + 1]);
    }

    // ================= Phase 3: V stream -> acc (barrier-free loop) =========
    const int half = tid & 1;    // 8-token half
    const int pd = tid >> 1;     // output dim (0..127)
    const int voff = tid * 8;    // pd*16 + half*8
    float acc[HPG] = {0.f, 0.f, 0.f, 0.f};
    float4 vb[4][2];
#pragma unroll
    for (int p = 0; p < 4; p++) {
        if (p < n_blk) {
            const float* vp = vc + ((size_t)bt_s[p] * NKV + g) * 2048 + voff;
            vb[p][0] = *(const float4*)vp;
            vb[p][1] = *(const float4*)(vp + 4);
        }
    }
    {
        int i = 0;
        for (; i + 4 <= n_blk; i += 4) {
#pragma unroll
            for (int u = 0; u < 4; u++) {
                const float4 a0 = vb[u][0], a1 = vb[u][1];
                if (i + u + 4 < n_blk) {
                    const float* vp = vc + ((size_t)bt_s[i + u + 4] * NKV + g) * 2048 + voff;
                    vb[u][0] = *(const float4*)vp;
                    vb[u][1] = *(const float4*)(vp + 4);
                }
                const float vv[8] = {a0.x, a0.y, a0.z, a0.w, a1.x, a1.y, a1.z, a1.w};
                const int pbase = (i + u) * BS + half * 8;
#pragma unroll
                for (int h = 0; h < HPG; h++) {
                    const float4 p0 = *(const float4*)&ls[h * CT + pbase];
                    const float4 p1 = *(const float4*)&ls[h * CT + pbase + 4];
                    float a = acc[h];
                    a = fmaf(p0.x, vv[0], a); a = fmaf(p0.y, vv[1], a);
                    a = fmaf(p0.z, vv[2], a); a = fmaf(p0.w, vv[3], a);
                    a = fmaf(p1.x, vv[4], a); a = fmaf(p1.y, vv[5], a);
                    a = fmaf(p1.z, vv[6], a); a = fmaf(p1.w, vv[7], a);
                    acc[h] = a;
                }
            }
        }
        const int rem = n_blk - i;
#pragma unroll
        for (int u = 0; u < 3; u++) {
            if (u < rem) {
                const float4 a0 = vb[u][0], a1 = vb[u][1];
                const float vv[8] = {a0.x, a0.y, a0.z, a0.w, a1.x, a1.y, a1.z, a1.w};
                const int pbase = (i + u) * BS + half * 8;
#pragma unroll
                for (int h = 0; h < HPG; h++) {
                    const float4 p0 = *(const float4*)&ls[h * CT + pbase];
                    const float4 p1 = *(const float4*)&ls[h * CT + pbase + 4];
                    float a = acc[h];
                    a = fmaf(p0.x, vv[0], a); a = fmaf(p0.y, vv[1], a);
                    a = fmaf(p0.z, vv[2], a); a = fmaf(p0.w, vv[3], a);
                    a = fmaf(p1.x, vv[4], a); a = fmaf(p1.y, vv[5], a);
                    a = fmaf(p1.z, vv[6], a); a = fmaf(p1.w, vv[7], a);
                    acc[h] = a;
                }
            }
        }
    }

    // ================= Write partials =======================================
    const int base = ((s * NKV + g) * NCHUNK + c) * HPG;
#pragma unroll
    for (int h = 0; h < HPG; h++) {
        const float tot = acc[h] + __shfl_xor_sync(0xffffffffu, acc[h], 1);
        if (half == 0) g_pacc[(size_t)(base + h) * DH + pd] = tot;
    }
}

__global__ __launch_bounds__(512) void pa_combine_kernel(
    const int* __restrict__ cl, float* __restrict__ out)
{
    const int g = blockIdx.x, s = blockIdx.y;
    const int tid = threadIdx.x;
    const int h = tid >> 7, d = tid & 127;
    const int len = cl[s];
    const int nc = min(NCHUNK, (len + CT - 1) / CT);
    const int base = (s * NKV + g) * NCHUNK;

    float2 ml[NCHUNK];
    float M = -1e30f;
    for (int c = 0; c < nc; c++) {
        ml[c] = g_pml[(base + c) * HPG + h];
        M = fmaxf(M, ml[c].x);
    }
    float L = 0.f, o = 0.f;
    for (int c = 0; c < nc; c++) {
        const float w = __expf(ml[c].x - M);
        L += ml[c].y * w;
        o += g_pacc[(size_t)((base + c) * HPG + h) * DH + d] * w;
    }
    out[((size_t)s * NHEAD + g * HPG + h) * DH + d] = o / L;
}

extern "C" void kernel_launch(void* const* d_in, const int* in_sizes, int n_in,
                              void* d_out, int out_size)
{
    const float* q  = (const float*)d_in[0];
    const float* kc = (const float*)d_in[1];
    const float* vc = (const float*)d_in[2];
    const int*   bt = (const int*)d_in[3];
    const int*   cl = (const int*)d_in[4];
    float* out = (float*)d_out;

    dim3 grid1(NCHUNK, NKV, NSEQ);   // 8 x 8 x 32 = 2048 CTAs
    pa_chunk_kernel<<<grid1, 256>>>(q, kc, vc, bt, cl);
    dim3 grid2(NKV, NSEQ);           // 8 x 32 = 256 CTAs
    pa_combine_kernel<<<grid2, 512>>>(cl, out);
}